// round 4
// baseline (speedup 1.0000x reference)
#include <cuda_runtime.h>

#define NN    10000
#define HEADS 4
#define F     256      // heads * 64, also input feature count
#define EMAX  340000   // 320000 edges + 10000 self loops, padded

// ---------------- persistent scratch (no allocation allowed) ----------------
__device__ float g_h[NN * F];      // transformed features h = in @ W
__device__ float g_feat[NN * F];   // activated layer output (input to next layer)
__device__ float g_as[NN * HEADS]; // per-node src attention logits
__device__ float g_ad[NN * HEADS]; // per-node dst attention logits
__device__ int   g_deg[NN];
__device__ int   g_fill[NN];
__device__ int   g_ptr[NN + 1];
__device__ int   g_srcb[EMAX];     // CSR-by-dst: src node per slot
__device__ int   g_is64;           // edge_index dtype flag (detected on device)

// ---------------- edge dtype detection ----------------
// int64 edge data: first 64 values (as long long) all lie in [0, NN).
// int32 edge data reinterpreted as long long: high word is another random
// index (nonzero w.p. ~0.9999 each) -> detected as NOT int64.
__global__ void detect_kernel(const void* eiv) {
    const long long* p = (const long long*)eiv;
    int ok = 1;
    for (int i = 0; i < 64; i++) {
        long long v = p[i];
        if (v < 0 || v >= NN) { ok = 0; break; }
    }
    g_is64 = ok;
}

__device__ __forceinline__ int edge_at(const void* eiv, int idx) {
    if (g_is64)
        return (int)((const long long*)eiv)[idx];
    else
        return ((const int*)eiv)[idx];
}

// ---------------- CSR build ----------------
__global__ void zero_kernel() {
    int t = blockIdx.x * blockDim.x + threadIdx.x;
    if (t < NN) { g_deg[t] = 0; g_fill[t] = 0; }
}

__global__ void count_kernel(const void* eiv, int E) {
    int t = blockIdx.x * blockDim.x + threadIdx.x;
    if (t < E) {
        atomicAdd(&g_deg[edge_at(eiv, E + t)], 1);
    } else if (t < E + NN) {
        atomicAdd(&g_deg[t - E], 1);  // self loop
    }
}

// exclusive scan of g_deg -> g_ptr, single block of 256 threads, shuffle-based
__global__ void scan_kernel() {
    __shared__ int wsum[8];
    const int CH = (NN + 255) / 256;  // 40 elements per thread
    int t = threadIdx.x;
    int base = t * CH;
    int tot = 0;
    for (int i = 0; i < CH; i++) {
        int idx = base + i;
        if (idx < NN) tot += g_deg[idx];
    }
    int lane = t & 31, wid = t >> 5;
    int v = tot;
    for (int off = 1; off < 32; off <<= 1) {
        int u = __shfl_up_sync(0xffffffffu, v, off);
        if (lane >= off) v += u;
    }
    if (lane == 31) wsum[wid] = v;
    __syncthreads();
    if (wid == 0) {
        int w = (lane < 8) ? wsum[lane] : 0;
        for (int off = 1; off < 8; off <<= 1) {
            int u = __shfl_up_sync(0xffffffffu, w, off);
            if (lane >= off) w += u;
        }
        if (lane < 8) wsum[lane] = w;
    }
    __syncthreads();
    int excl = v - tot + (wid ? wsum[wid - 1] : 0);
    int run = excl;
    for (int i = 0; i < CH; i++) {
        int idx = base + i;
        if (idx < NN) { g_ptr[idx] = run; run += g_deg[idx]; }
    }
    if (t == 255) g_ptr[NN] = run;   // threads past NN carry excl == total
}

__global__ void scatter_kernel(const void* eiv, int E) {
    int t = blockIdx.x * blockDim.x + threadIdx.x;
    if (t < E) {
        int s = edge_at(eiv, t);
        int d = edge_at(eiv, E + t);
        int p = atomicAdd(&g_fill[d], 1);
        g_srcb[g_ptr[d] + p] = s;
    } else if (t < E + NN) {
        int i = t - E;
        int p = atomicAdd(&g_fill[i], 1);
        g_srcb[g_ptr[i] + p] = i;
    }
}

// ------- GEMM + fused attention dots: g_h = A @ B, per-tile a_s/a_d ---------
// Block computes a 64(m) x 64(n) tile; blockIdx.y is the head (F/64 == HEADS).
template <bool USE_FEAT>
__global__ void __launch_bounds__(256) gemm_kernel(const float* Aext,
                                                   const float* B,
                                                   const float* att_s,
                                                   const float* att_d) {
    __shared__ float As[16][64];  // [k][m]
    __shared__ float Bs[16][64];  // [k][n]
    int tid = threadIdx.x;
    int m0 = blockIdx.x * 64, n0 = blockIdx.y * 64;
    int hd = blockIdx.y;
    int tx = tid & 15, ty = tid >> 4;
    int aRow = tid >> 2, aCol = (tid & 3) * 4;
    int bRow = tid >> 4, bCol = (tid & 15) * 4;
    bool aOK = (m0 + aRow) < NN;
    long aBase = (long)(m0 + aRow) * F;

    float acc[4][4];
#pragma unroll
    for (int i = 0; i < 4; i++)
#pragma unroll
        for (int j = 0; j < 4; j++) acc[i][j] = 0.f;

    for (int kt = 0; kt < F; kt += 16) {
        float4 av = make_float4(0.f, 0.f, 0.f, 0.f);
        if (aOK) {
            if (USE_FEAT)
                av = *(const float4*)(&g_feat[aBase + kt + aCol]);
            else
                av = *(const float4*)(Aext + aBase + kt + aCol);
        }
        As[aCol + 0][aRow] = av.x;
        As[aCol + 1][aRow] = av.y;
        As[aCol + 2][aRow] = av.z;
        As[aCol + 3][aRow] = av.w;
        *(float4*)&Bs[bRow][bCol] = *(const float4*)(B + (long)(kt + bRow) * F + n0 + bCol);
        __syncthreads();
#pragma unroll
        for (int kk = 0; kk < 16; kk++) {
            float a0 = As[kk][ty * 4 + 0];
            float a1 = As[kk][ty * 4 + 1];
            float a2 = As[kk][ty * 4 + 2];
            float a3 = As[kk][ty * 4 + 3];
            float4 b = *(float4*)&Bs[kk][tx * 4];
            acc[0][0] += a0 * b.x; acc[0][1] += a0 * b.y; acc[0][2] += a0 * b.z; acc[0][3] += a0 * b.w;
            acc[1][0] += a1 * b.x; acc[1][1] += a1 * b.y; acc[1][2] += a1 * b.z; acc[1][3] += a1 * b.w;
            acc[2][0] += a2 * b.x; acc[2][1] += a2 * b.y; acc[2][2] += a2 * b.z; acc[2][3] += a2 * b.w;
            acc[3][0] += a3 * b.x; acc[3][1] += a3 * b.y; acc[3][2] += a3 * b.z; acc[3][3] += a3 * b.w;
        }
        __syncthreads();
    }

    // attention vector slices for this thread's 4 columns
    float vs0 = att_s[hd * 64 + tx * 4 + 0], vd0 = att_d[hd * 64 + tx * 4 + 0];
    float vs1 = att_s[hd * 64 + tx * 4 + 1], vd1 = att_d[hd * 64 + tx * 4 + 1];
    float vs2 = att_s[hd * 64 + tx * 4 + 2], vd2 = att_d[hd * 64 + tx * 4 + 2];
    float vs3 = att_s[hd * 64 + tx * 4 + 3], vd3 = att_d[hd * 64 + tx * 4 + 3];

#pragma unroll
    for (int i = 0; i < 4; i++) {
        int m = m0 + ty * 4 + i;
        bool mOK = m < NN;
        if (mOK) {
            float4 v = make_float4(acc[i][0], acc[i][1], acc[i][2], acc[i][3]);
            *(float4*)&g_h[(long)m * F + n0 + tx * 4] = v;
        }
        // fused dot: reduce acc[i][:] * att over the 16 tx-threads (half-warp)
        float ps = acc[i][0] * vs0 + acc[i][1] * vs1 + acc[i][2] * vs2 + acc[i][3] * vs3;
        float pd = acc[i][0] * vd0 + acc[i][1] * vd1 + acc[i][2] * vd2 + acc[i][3] * vd3;
#pragma unroll
        for (int off = 8; off; off >>= 1) {
            ps += __shfl_xor_sync(0xffffffffu, ps, off);
            pd += __shfl_xor_sync(0xffffffffu, pd, off);
        }
        if (tx == 0 && mOK) {
            g_as[m * HEADS + hd] = ps;
            g_ad[m * HEADS + hd] = pd;
        }
    }
}

// ---------------- fused softmax + aggregation: one warp per (node, head) -----
template <bool TO_FEAT>
__global__ void agg_kernel(const float* bias, float* outext) {
    int gw = (blockIdx.x * blockDim.x + threadIdx.x) >> 5;
    int lane = threadIdx.x & 31;
    if (gw >= NN * HEADS) return;
    int n = gw >> 2, hd = gw & 3;
    int beg = g_ptr[n], end = g_ptr[n + 1];
    float ad = g_ad[n * HEADS + hd];

    // pass 1: online (max, sum) over incoming edges, lane-strided
    float m = -1e30f, s = 0.f;
    for (int j = beg + lane; j < end; j += 32) {
        int src = g_srcb[j];
        float e = g_as[src * HEADS + hd] + ad;
        e = (e > 0.f) ? e : 0.2f * e;   // leaky_relu(0.2)
        float mn = fmaxf(m, e);
        s = s * __expf(m - mn) + __expf(e - mn);
        m = mn;
    }
#pragma unroll
    for (int off = 16; off; off >>= 1) {
        float m2 = __shfl_xor_sync(0xffffffffu, m, off);
        float s2 = __shfl_xor_sync(0xffffffffu, s, off);
        float mn = fmaxf(m, m2);
        s = s * __expf(m - mn) + s2 * __expf(m2 - mn);
        m = mn;
    }
    float inv = 1.f / (s + 1e-16f);

    // pass 2: weighted gather-accumulate of h[src], 2 channels per lane
    const int hoff = hd * 64;
    float acc0 = 0.f, acc1 = 0.f;
    for (int j = beg; j < end; ++j) {
        int src = g_srcb[j];                          // broadcast load
        float e = g_as[src * HEADS + hd] + ad;        // broadcast load
        e = (e > 0.f) ? e : 0.2f * e;
        float w = __expf(e - m) * inv;
        const float* hp = g_h + (long)src * F + hoff;
        acc0 += w * hp[lane];
        acc1 += w * hp[lane + 32];
    }

    int col = hoff + lane;
    float v0 = acc0 + bias[col];
    float v1 = acc1 + bias[col + 32];
    v0 = (v0 > 0.f) ? v0 : (__expf(v0) - 1.f);  // ELU
    v1 = (v1 > 0.f) ? v1 : (__expf(v1) - 1.f);
    if (TO_FEAT) {
        g_feat[(long)n * F + col] = v0;
        g_feat[(long)n * F + col + 32] = v1;
    } else {
        float* op = outext + (long)n * F;
        op[col] = v0;
        op[col + 32] = v1;
    }
}

// ---------------- orchestration ----------------
extern "C" void kernel_launch(void* const* d_in, const int* in_sizes, int n_in,
                              void* d_out, int out_size) {
    const float* x   = (const float*)d_in[0];
    const void*  ei  = d_in[1];
    const float* W1  = (const float*)d_in[2];
    const float* a1s = (const float*)d_in[3];
    const float* a1d = (const float*)d_in[4];
    const float* b1  = (const float*)d_in[5];
    const float* W2  = (const float*)d_in[6];
    const float* a2s = (const float*)d_in[7];
    const float* a2d = (const float*)d_in[8];
    const float* b2  = (const float*)d_in[9];
    const float* W3  = (const float*)d_in[10];
    const float* a3s = (const float*)d_in[11];
    const float* a3d = (const float*)d_in[12];
    const float* b3  = (const float*)d_in[13];
    float* out = (float*)d_out;
    int E = in_sizes[1] / 2;
    int tot = E + NN;

    // CSR build (by dst, self loops appended)
    detect_kernel<<<1, 1>>>(ei);
    zero_kernel<<<(NN + 255) / 256, 256>>>();
    count_kernel<<<(tot + 255) / 256, 256>>>(ei, E);
    scan_kernel<<<1, 256>>>();
    scatter_kernel<<<(tot + 255) / 256, 256>>>(ei, E);

    dim3 ggrid((NN + 63) / 64, F / 64);
    int warpBlocks = (NN * HEADS * 32 + 255) / 256;

    // layer 1: input = x, output -> g_feat
    gemm_kernel<false><<<ggrid, 256>>>(x, W1, a1s, a1d);
    agg_kernel<true><<<warpBlocks, 256>>>(b1, nullptr);

    // layer 2: input = g_feat, output -> g_feat
    gemm_kernel<true><<<ggrid, 256>>>(nullptr, W2, a2s, a2d);
    agg_kernel<true><<<warpBlocks, 256>>>(b2, nullptr);

    // layer 3: input = g_feat, output -> d_out
    gemm_kernel<true><<<ggrid, 256>>>(nullptr, W3, a3s, a3d);
    agg_kernel<false><<<warpBlocks, 256>>>(b3, out);
}

// round 6
// speedup vs baseline: 1.2971x; 1.2971x over previous
#include <cuda_runtime.h>
#include <cstdint>

#define NN    10000
#define HEADS 4
#define F     256      // heads * 64, also input feature count
#define EMAX  340000   // 320000 edges + 10000 self loops, padded

// ---------------- persistent scratch (no allocation allowed) ----------------
__device__ float g_h[NN * F];      // transformed features h = in @ W
__device__ float g_feat[NN * F];   // activated layer output (input to next layer)
__device__ float g_as[NN * HEADS]; // per-node src attention logits
__device__ float g_ad[NN * HEADS]; // per-node dst attention logits
__device__ int   g_deg[NN];
__device__ int   g_fill[NN];
__device__ int   g_ptr[NN + 1];
__device__ int   g_srcb[EMAX];     // CSR-by-dst: src node per slot
__device__ int   g_is64;           // edge_index dtype flag (detected on device)

// ---------------- zero + edge dtype detection ----------------
__global__ void zero_kernel(const void* eiv) {
    int t = blockIdx.x * blockDim.x + threadIdx.x;
    if (t < NN) { g_deg[t] = 0; g_fill[t] = 0; }
    if (blockIdx.x == 0 && threadIdx.x == 0) {
        // int64 edges: first 64 values (as long long) all in [0, NN).
        const long long* p = (const long long*)eiv;
        int ok = 1;
        for (int i = 0; i < 64; i++) {
            long long v = p[i];
            if (v < 0 || v >= NN) { ok = 0; break; }
        }
        g_is64 = ok;
    }
}

__device__ __forceinline__ int edge_at(const void* eiv, int idx) {
    if (g_is64)
        return (int)((const long long*)eiv)[idx];
    else
        return ((const int*)eiv)[idx];
}

// ---------------- CSR build ----------------
__global__ void count_kernel(const void* eiv, int E) {
    int t = blockIdx.x * blockDim.x + threadIdx.x;
    if (t < E) {
        atomicAdd(&g_deg[edge_at(eiv, E + t)], 1);
    } else if (t < E + NN) {
        atomicAdd(&g_deg[t - E], 1);  // self loop
    }
}

// exclusive scan of g_deg -> g_ptr, single block, smem-staged + shuffle
__global__ void scan_kernel() {
    __shared__ int sdeg[NN];
    __shared__ int wsum[8];
    const int CH = (NN + 255) / 256;  // 40
    int t = threadIdx.x;
    for (int i = t; i < NN; i += 256) sdeg[i] = g_deg[i];  // coalesced
    __syncthreads();

    int base = t * CH;
    int tot = 0;
    for (int i = 0; i < CH; i++) {
        int idx = base + i;
        if (idx < NN) tot += sdeg[idx];
    }
    int lane = t & 31, wid = t >> 5;
    int v = tot;
    for (int off = 1; off < 32; off <<= 1) {
        int u = __shfl_up_sync(0xffffffffu, v, off);
        if (lane >= off) v += u;
    }
    if (lane == 31) wsum[wid] = v;
    __syncthreads();
    if (wid == 0) {
        int w = (lane < 8) ? wsum[lane] : 0;
        for (int off = 1; off < 8; off <<= 1) {
            int u = __shfl_up_sync(0xffffffffu, w, off);
            if (lane >= off) w += u;
        }
        if (lane < 8) wsum[lane] = w;
    }
    __syncthreads();
    int run = v - tot + (wid ? wsum[wid - 1] : 0);
    for (int i = 0; i < CH; i++) {
        int idx = base + i;
        if (idx < NN) {
            int d = sdeg[idx];
            sdeg[idx] = run;   // in-place exclusive prefix
            run += d;
        }
    }
    if (t == 255) g_ptr[NN] = run;
    __syncthreads();
    for (int i = t; i < NN; i += 256) g_ptr[i] = sdeg[i];  // coalesced
}

__global__ void scatter_kernel(const void* eiv, int E) {
    int t = blockIdx.x * blockDim.x + threadIdx.x;
    if (t < E) {
        int s = edge_at(eiv, t);
        int d = edge_at(eiv, E + t);
        int p = atomicAdd(&g_fill[d], 1);
        g_srcb[g_ptr[d] + p] = s;
    } else if (t < E + NN) {
        int i = t - E;
        int p = atomicAdd(&g_fill[i], 1);
        g_srcb[g_ptr[i] + p] = i;
    }
}

// ---------------- tf32 tensor-core GEMM: g_h = A @ B ------------------------
// Block tile 128(m) x 64(n), 8 warps as 4(m) x 2(n), warp tile 32x32 built
// from 2x4 m16n8k8 tf32 MMA fragments. K staged in 32-wide smem chunks,
// fp32 -> tf32 converted once at the smem store.
__device__ __forceinline__ uint32_t f2tf32(float f) {
    uint32_t r;
    asm("cvt.rna.tf32.f32 %0, %1;" : "=r"(r) : "f"(f));
    return r;
}

template <bool USE_FEAT>
__global__ void __launch_bounds__(256) gemm_tf32_kernel(const float* Aext,
                                                        const float* B) {
    __shared__ uint32_t As[128][36];  // 128 x 32, pad to 36 (16B-aligned rows)
    __shared__ uint32_t Bs[32][68];   // 32 x 64, pad to 68
    int tid = threadIdx.x;
    int wid = tid >> 5, lane = tid & 31;
    int wm = wid >> 1, wn = wid & 1;          // warp coords: 4 x 2
    int m0 = blockIdx.x * 128, n0 = blockIdx.y * 64;

    float c[2][4][4];
#pragma unroll
    for (int f = 0; f < 2; f++)
#pragma unroll
        for (int g = 0; g < 4; g++)
#pragma unroll
            for (int i = 0; i < 4; i++) c[f][g][i] = 0.f;

    int lr = lane >> 2;   // 0..7
    int lc = lane & 3;    // 0..3

    for (int kt = 0; kt < F; kt += 32) {
        // stage A tile (128 x 32): 1024 float4 over 256 threads = 4 each
#pragma unroll
        for (int i = 0; i < 4; i++) {
            int id = tid + i * 256;
            int row = id >> 3, c4 = (id & 7) * 4;
            int m = m0 + row;
            float4 v = make_float4(0.f, 0.f, 0.f, 0.f);
            if (m < NN) {
                long off = (long)m * F + kt + c4;
                v = USE_FEAT ? *(const float4*)(&g_feat[off])
                             : *(const float4*)(Aext + off);
            }
            As[row][c4 + 0] = f2tf32(v.x);
            As[row][c4 + 1] = f2tf32(v.y);
            As[row][c4 + 2] = f2tf32(v.z);
            As[row][c4 + 3] = f2tf32(v.w);
        }
        // stage B tile (32 x 64): 512 float4 over 256 threads = 2 each
#pragma unroll
        for (int i = 0; i < 2; i++) {
            int id = tid + i * 256;
            int row = id >> 4, c4 = (id & 15) * 4;
            float4 v = *(const float4*)(B + (long)(kt + row) * F + n0 + c4);
            Bs[row][c4 + 0] = f2tf32(v.x);
            Bs[row][c4 + 1] = f2tf32(v.y);
            Bs[row][c4 + 2] = f2tf32(v.z);
            Bs[row][c4 + 3] = f2tf32(v.w);
        }
        __syncthreads();

#pragma unroll
        for (int s = 0; s < 4; s++) {
            int kb = s * 8;
            uint32_t a[2][4];
#pragma unroll
            for (int f = 0; f < 2; f++) {
                int rb = wm * 32 + f * 16;
                a[f][0] = As[rb + lr][kb + lc];
                a[f][1] = As[rb + lr + 8][kb + lc];
                a[f][2] = As[rb + lr][kb + lc + 4];
                a[f][3] = As[rb + lr + 8][kb + lc + 4];
            }
            uint32_t b[4][2];
#pragma unroll
            for (int g = 0; g < 4; g++) {
                int cb = wn * 32 + g * 8;
                b[g][0] = Bs[kb + lc][cb + lr];
                b[g][1] = Bs[kb + lc + 4][cb + lr];
            }
#pragma unroll
            for (int f = 0; f < 2; f++)
#pragma unroll
                for (int g = 0; g < 4; g++) {
                    asm volatile(
                        "mma.sync.aligned.m16n8k8.row.col.f32.tf32.tf32.f32 "
                        "{%0,%1,%2,%3}, {%4,%5,%6,%7}, {%8,%9}, {%0,%1,%2,%3};"
                        : "+f"(c[f][g][0]), "+f"(c[f][g][1]),
                          "+f"(c[f][g][2]), "+f"(c[f][g][3])
                        : "r"(a[f][0]), "r"(a[f][1]), "r"(a[f][2]), "r"(a[f][3]),
                          "r"(b[g][0]), "r"(b[g][1]));
                }
        }
        __syncthreads();
    }

    // epilogue: write g_h
#pragma unroll
    for (int f = 0; f < 2; f++) {
        int row0 = m0 + wm * 32 + f * 16 + lr;
#pragma unroll
        for (int g = 0; g < 4; g++) {
            int col = n0 + wn * 32 + g * 8 + lc * 2;
            if (row0 < NN)
                *(float2*)&g_h[(long)row0 * F + col] = make_float2(c[f][g][0], c[f][g][1]);
            if (row0 + 8 < NN)
                *(float2*)&g_h[(long)(row0 + 8) * F + col] = make_float2(c[f][g][2], c[f][g][3]);
        }
    }
}

// ---------------- attention dot products: one warp per (node, head) ----------
__global__ void attdot_kernel(const float* att_s, const float* att_d) {
    int gw = (blockIdx.x * blockDim.x + threadIdx.x) >> 5;
    int lane = threadIdx.x & 31;
    if (gw >= NN * HEADS) return;
    int n = gw >> 2, hd = gw & 3;
    const float* hp = g_h + (long)n * F + hd * 64;
    float x0 = hp[lane], x1 = hp[lane + 32];
    float s0 = x0 * att_s[hd * 64 + lane] + x1 * att_s[hd * 64 + lane + 32];
    float d0 = x0 * att_d[hd * 64 + lane] + x1 * att_d[hd * 64 + lane + 32];
#pragma unroll
    for (int off = 16; off; off >>= 1) {
        s0 += __shfl_xor_sync(0xffffffffu, s0, off);
        d0 += __shfl_xor_sync(0xffffffffu, d0, off);
    }
    if (lane == 0) { g_as[gw] = s0; g_ad[gw] = d0; }
}

// ---------------- fused softmax + aggregation: one warp per (node, head) -----
template <bool TO_FEAT>
__global__ void agg_kernel(const float* bias, float* outext) {
    int gw = (blockIdx.x * blockDim.x + threadIdx.x) >> 5;
    int lane = threadIdx.x & 31;
    if (gw >= NN * HEADS) return;
    int n = gw >> 2, hd = gw & 3;
    int beg = g_ptr[n], end = g_ptr[n + 1];
    float ad = g_ad[n * HEADS + hd];

    // pass 1: online (max, sum) over incoming edges, lane-strided
    float m = -1e30f, s = 0.f;
    for (int j = beg + lane; j < end; j += 32) {
        int src = g_srcb[j];
        float e = g_as[src * HEADS + hd] + ad;
        e = (e > 0.f) ? e : 0.2f * e;   // leaky_relu(0.2)
        float mn = fmaxf(m, e);
        s = s * __expf(m - mn) + __expf(e - mn);
        m = mn;
    }
#pragma unroll
    for (int off = 16; off; off >>= 1) {
        float m2 = __shfl_xor_sync(0xffffffffu, m, off);
        float s2 = __shfl_xor_sync(0xffffffffu, s, off);
        float mn = fmaxf(m, m2);
        s = s * __expf(m - mn) + s2 * __expf(m2 - mn);
        m = mn;
    }
    float inv = 1.f / (s + 1e-16f);

    // pass 2: weighted gather-accumulate of h[src], 2 channels per lane
    const int hoff = hd * 64;
    float acc0 = 0.f, acc1 = 0.f;
    for (int j = beg; j < end; ++j) {
        int src = g_srcb[j];                          // broadcast load
        float e = g_as[src * HEADS + hd] + ad;        // broadcast load
        e = (e > 0.f) ? e : 0.2f * e;
        float w = __expf(e - m) * inv;
        const float* hp = g_h + (long)src * F + hoff;
        acc0 += w * hp[lane];
        acc1 += w * hp[lane + 32];
    }

    int col = hoff + lane;
    float v0 = acc0 + bias[col];
    float v1 = acc1 + bias[col + 32];
    v0 = (v0 > 0.f) ? v0 : (__expf(v0) - 1.f);  // ELU
    v1 = (v1 > 0.f) ? v1 : (__expf(v1) - 1.f);
    if (TO_FEAT) {
        g_feat[(long)n * F + col] = v0;
        g_feat[(long)n * F + col + 32] = v1;
    } else {
        float* op = outext + (long)n * F;
        op[col] = v0;
        op[col + 32] = v1;
    }
}

// ---------------- orchestration ----------------
extern "C" void kernel_launch(void* const* d_in, const int* in_sizes, int n_in,
                              void* d_out, int out_size) {
    const float* x   = (const float*)d_in[0];
    const void*  ei  = d_in[1];
    const float* W1  = (const float*)d_in[2];
    const float* a1s = (const float*)d_in[3];
    const float* a1d = (const float*)d_in[4];
    const float* b1  = (const float*)d_in[5];
    const float* W2  = (const float*)d_in[6];
    const float* a2s = (const float*)d_in[7];
    const float* a2d = (const float*)d_in[8];
    const float* b2  = (const float*)d_in[9];
    const float* W3  = (const float*)d_in[10];
    const float* a3s = (const float*)d_in[11];
    const float* a3d = (const float*)d_in[12];
    const float* b3  = (const float*)d_in[13];
    float* out = (float*)d_out;
    int E = in_sizes[1] / 2;
    int tot = E + NN;

    // CSR build (by dst, self loops appended)
    zero_kernel<<<(NN + 255) / 256, 256>>>(ei);
    count_kernel<<<(tot + 255) / 256, 256>>>(ei, E);
    scan_kernel<<<1, 256>>>();
    scatter_kernel<<<(tot + 255) / 256, 256>>>(ei, E);

    dim3 ggrid((NN + 127) / 128, F / 64);
    int warpBlocks = (NN * HEADS * 32 + 255) / 256;

    // layer 1: input = x, output -> g_feat
    gemm_tf32_kernel<false><<<ggrid, 256>>>(x, W1);
    attdot_kernel<<<warpBlocks, 256>>>(a1s, a1d);
    agg_kernel<true><<<warpBlocks, 256>>>(b1, nullptr);

    // layer 2: input = g_feat, output -> g_feat
    gemm_tf32_kernel<true><<<ggrid, 256>>>(nullptr, W2);
    attdot_kernel<<<warpBlocks, 256>>>(a2s, a2d);
    agg_kernel<true><<<warpBlocks, 256>>>(b2, nullptr);

    // layer 3: input = g_feat, output -> d_out
    gemm_tf32_kernel<true><<<ggrid, 256>>>(nullptr, W3);
    attdot_kernel<<<warpBlocks, 256>>>(a3s, a3d);
    agg_kernel<false><<<warpBlocks, 256>>>(b3, out);
}

// round 7
// speedup vs baseline: 1.5134x; 1.1667x over previous
#include <cuda_runtime.h>
#include <cuda_fp16.h>
#include <cstdint>

#define NN    10000
#define HEADS 4
#define F     256      // heads * 64, also input feature count
#define EMAX  340000   // 320000 edges + 10000 self loops, padded

// ---------------- persistent scratch (no allocation allowed) ----------------
__device__ uint32_t g_h16[NN * (F / 2)];   // h as half2 pairs: [node][128]
__device__ float    g_feat[NN * F];        // activated layer output (fp32)
__device__ float    g_as[NN * HEADS];      // per-node src attention logits
__device__ float    g_ad[NN * HEADS];      // per-node dst attention logits
__device__ float    g_m[NN * HEADS];       // softmax max per (node, head)
__device__ float    g_inv[NN * HEADS];     // 1/(sum+eps) per (node, head)
__device__ float    g_w[EMAX * HEADS];     // normalized edge weight per (slot, head)
__device__ int      g_deg[NN];
__device__ int      g_fill[NN];
__device__ int      g_ptr[NN + 1];
__device__ int      g_srcb[EMAX];          // CSR-by-dst: src node per slot
__device__ int      g_dstb[EMAX];          // CSR-by-dst: dst node per slot
__device__ int      g_is64;                // edge_index dtype flag

// ---------------- zero + edge dtype detection ----------------
__global__ void zero_kernel(const void* eiv) {
    int t = blockIdx.x * blockDim.x + threadIdx.x;
    if (t < NN) { g_deg[t] = 0; g_fill[t] = 0; }
    if (blockIdx.x == 0 && threadIdx.x == 0) {
        const long long* p = (const long long*)eiv;
        int ok = 1;
        for (int i = 0; i < 64; i++) {
            long long v = p[i];
            if (v < 0 || v >= NN) { ok = 0; break; }
        }
        g_is64 = ok;
    }
}

__device__ __forceinline__ int edge_at(const void* eiv, int idx) {
    if (g_is64)
        return (int)((const long long*)eiv)[idx];
    else
        return ((const int*)eiv)[idx];
}

// ---------------- CSR build ----------------
__global__ void count_kernel(const void* eiv, int E) {
    int t = blockIdx.x * blockDim.x + threadIdx.x;
    if (t < E) {
        atomicAdd(&g_deg[edge_at(eiv, E + t)], 1);
    } else if (t < E + NN) {
        atomicAdd(&g_deg[t - E], 1);  // self loop
    }
}

__global__ void scan_kernel() {
    __shared__ int sdeg[NN];
    __shared__ int wsum[8];
    const int CH = (NN + 255) / 256;  // 40
    int t = threadIdx.x;
    for (int i = t; i < NN; i += 256) sdeg[i] = g_deg[i];
    __syncthreads();

    int base = t * CH;
    int tot = 0;
    for (int i = 0; i < CH; i++) {
        int idx = base + i;
        if (idx < NN) tot += sdeg[idx];
    }
    int lane = t & 31, wid = t >> 5;
    int v = tot;
    for (int off = 1; off < 32; off <<= 1) {
        int u = __shfl_up_sync(0xffffffffu, v, off);
        if (lane >= off) v += u;
    }
    if (lane == 31) wsum[wid] = v;
    __syncthreads();
    if (wid == 0) {
        int w = (lane < 8) ? wsum[lane] : 0;
        for (int off = 1; off < 8; off <<= 1) {
            int u = __shfl_up_sync(0xffffffffu, w, off);
            if (lane >= off) w += u;
        }
        if (lane < 8) wsum[lane] = w;
    }
    __syncthreads();
    int run = v - tot + (wid ? wsum[wid - 1] : 0);
    for (int i = 0; i < CH; i++) {
        int idx = base + i;
        if (idx < NN) {
            int d = sdeg[idx];
            sdeg[idx] = run;
            run += d;
        }
    }
    if (t == 255) g_ptr[NN] = run;
    __syncthreads();
    for (int i = t; i < NN; i += 256) g_ptr[i] = sdeg[i];
}

__global__ void scatter_kernel(const void* eiv, int E) {
    int t = blockIdx.x * blockDim.x + threadIdx.x;
    if (t < E) {
        int s = edge_at(eiv, t);
        int d = edge_at(eiv, E + t);
        int p = atomicAdd(&g_fill[d], 1);
        int slot = g_ptr[d] + p;
        g_srcb[slot] = s;
        g_dstb[slot] = d;
    } else if (t < E + NN) {
        int i = t - E;
        int p = atomicAdd(&g_fill[i], 1);
        int slot = g_ptr[i] + p;
        g_srcb[slot] = i;
        g_dstb[slot] = i;
    }
}

// ------ tf32 tensor-core GEMM + fused attention dots + fp16 h output --------
// Block tile 128(m) x 64(n); blockIdx.y == head. 8 warps as 4(m) x 2(n).
__device__ __forceinline__ uint32_t f2tf32(float f) {
    uint32_t r;
    asm("cvt.rna.tf32.f32 %0, %1;" : "=r"(r) : "f"(f));
    return r;
}

template <bool USE_FEAT>
__global__ void __launch_bounds__(256) gemm_tf32_kernel(const float* Aext,
                                                        const float* B,
                                                        const float* att_s,
                                                        const float* att_d) {
    __shared__ uint32_t As[128][36];
    __shared__ uint32_t Bs[32][68];
    __shared__ float sAs[128], sAd[128];
    int tid = threadIdx.x;
    int wid = tid >> 5, lane = tid & 31;
    int wm = wid >> 1, wn = wid & 1;
    int m0 = blockIdx.x * 128, n0 = blockIdx.y * 64;
    int hd = blockIdx.y;

    if (tid < 128) { sAs[tid] = 0.f; sAd[tid] = 0.f; }

    float c[2][4][4];
#pragma unroll
    for (int f = 0; f < 2; f++)
#pragma unroll
        for (int g = 0; g < 4; g++)
#pragma unroll
            for (int i = 0; i < 4; i++) c[f][g][i] = 0.f;

    int lr = lane >> 2;
    int lc = lane & 3;

    for (int kt = 0; kt < F; kt += 32) {
#pragma unroll
        for (int i = 0; i < 4; i++) {
            int id = tid + i * 256;
            int row = id >> 3, c4 = (id & 7) * 4;
            int m = m0 + row;
            float4 v = make_float4(0.f, 0.f, 0.f, 0.f);
            if (m < NN) {
                long off = (long)m * F + kt + c4;
                v = USE_FEAT ? *(const float4*)(&g_feat[off])
                             : *(const float4*)(Aext + off);
            }
            As[row][c4 + 0] = f2tf32(v.x);
            As[row][c4 + 1] = f2tf32(v.y);
            As[row][c4 + 2] = f2tf32(v.z);
            As[row][c4 + 3] = f2tf32(v.w);
        }
#pragma unroll
        for (int i = 0; i < 2; i++) {
            int id = tid + i * 256;
            int row = id >> 4, c4 = (id & 15) * 4;
            float4 v = *(const float4*)(B + (long)(kt + row) * F + n0 + c4);
            Bs[row][c4 + 0] = f2tf32(v.x);
            Bs[row][c4 + 1] = f2tf32(v.y);
            Bs[row][c4 + 2] = f2tf32(v.z);
            Bs[row][c4 + 3] = f2tf32(v.w);
        }
        __syncthreads();

#pragma unroll
        for (int s = 0; s < 4; s++) {
            int kb = s * 8;
            uint32_t a[2][4];
#pragma unroll
            for (int f = 0; f < 2; f++) {
                int rb = wm * 32 + f * 16;
                a[f][0] = As[rb + lr][kb + lc];
                a[f][1] = As[rb + lr + 8][kb + lc];
                a[f][2] = As[rb + lr][kb + lc + 4];
                a[f][3] = As[rb + lr + 8][kb + lc + 4];
            }
            uint32_t b[4][2];
#pragma unroll
            for (int g = 0; g < 4; g++) {
                int cb = wn * 32 + g * 8;
                b[g][0] = Bs[kb + lc][cb + lr];
                b[g][1] = Bs[kb + lc + 4][cb + lr];
            }
#pragma unroll
            for (int f = 0; f < 2; f++)
#pragma unroll
                for (int g = 0; g < 4; g++) {
                    asm volatile(
                        "mma.sync.aligned.m16n8k8.row.col.f32.tf32.tf32.f32 "
                        "{%0,%1,%2,%3}, {%4,%5,%6,%7}, {%8,%9}, {%0,%1,%2,%3};"
                        : "+f"(c[f][g][0]), "+f"(c[f][g][1]),
                          "+f"(c[f][g][2]), "+f"(c[f][g][3])
                        : "r"(a[f][0]), "r"(a[f][1]), "r"(a[f][2]), "r"(a[f][3]),
                          "r"(b[g][0]), "r"(b[g][1]));
                }
        }
        __syncthreads();
    }

    // epilogue: write h as half2, and fused per-row attention dots (fp32)
#pragma unroll
    for (int f = 0; f < 2; f++) {
        int row0 = m0 + wm * 32 + f * 16 + lr;
        float ps0 = 0.f, ps1 = 0.f, pd0 = 0.f, pd1 = 0.f;
#pragma unroll
        for (int g = 0; g < 4; g++) {
            int colh = wn * 32 + g * 8 + lc * 2;        // column within head
            float as0 = att_s[hd * 64 + colh], as1 = att_s[hd * 64 + colh + 1];
            float ad0 = att_d[hd * 64 + colh], ad1 = att_d[hd * 64 + colh + 1];
            ps0 += c[f][g][0] * as0 + c[f][g][1] * as1;
            pd0 += c[f][g][0] * ad0 + c[f][g][1] * ad1;
            ps1 += c[f][g][2] * as0 + c[f][g][3] * as1;
            pd1 += c[f][g][2] * ad0 + c[f][g][3] * ad1;
            uint32_t hidx = (uint32_t)(wn * 16 + g * 4 + lc) + hd * 32;
            if (row0 < NN) {
                __half2 hv = __floats2half2_rn(c[f][g][0], c[f][g][1]);
                g_h16[(long)row0 * 128 + hidx] = *(uint32_t*)&hv;
            }
            if (row0 + 8 < NN) {
                __half2 hv = __floats2half2_rn(c[f][g][2], c[f][g][3]);
                g_h16[(long)(row0 + 8) * 128 + hidx] = *(uint32_t*)&hv;
            }
        }
        // reduce over lc (4 lanes share a row)
#pragma unroll
        for (int off = 1; off <= 2; off <<= 1) {
            ps0 += __shfl_xor_sync(0xffffffffu, ps0, off);
            ps1 += __shfl_xor_sync(0xffffffffu, ps1, off);
            pd0 += __shfl_xor_sync(0xffffffffu, pd0, off);
            pd1 += __shfl_xor_sync(0xffffffffu, pd1, off);
        }
        if (lc == 0) {
            int r = wm * 32 + f * 16 + lr;
            atomicAdd(&sAs[r], ps0);
            atomicAdd(&sAd[r], pd0);
            atomicAdd(&sAs[r + 8], ps1);
            atomicAdd(&sAd[r + 8], pd1);
        }
    }
    __syncthreads();
    if (tid < 128) {
        int m = m0 + tid;
        if (m < NN) {
            g_as[m * HEADS + hd] = sAs[tid];
            g_ad[m * HEADS + hd] = sAd[tid];
        }
    }
}

// ------- pass 1: softmax (max, sum) — one warp per node, all 4 heads --------
__global__ void agg1_kernel() {
    int n = (blockIdx.x * blockDim.x + threadIdx.x) >> 5;
    int lane = threadIdx.x & 31;
    if (n >= NN) return;
    int hd = lane & 3, sub = lane >> 2;
    int beg = g_ptr[n], end = g_ptr[n + 1];
    float ad = g_ad[n * HEADS + hd];

    float m = -1e30f, s = 0.f;
    for (int j = beg + sub; j < end; j += 8) {
        int src = g_srcb[j];
        float e = g_as[src * HEADS + hd] + ad;
        e = (e > 0.f) ? e : 0.2f * e;
        float mn = fmaxf(m, e);
        s = s * __expf(m - mn) + __expf(e - mn);
        m = mn;
    }
#pragma unroll
    for (int off = 4; off <= 16; off <<= 1) {
        float m2 = __shfl_xor_sync(0xffffffffu, m, off);
        float s2 = __shfl_xor_sync(0xffffffffu, s, off);
        float mn = fmaxf(m, m2);
        s = s * __expf(m - mn) + s2 * __expf(m2 - mn);
        m = mn;
    }
    if (lane < 4) {
        g_m[n * HEADS + hd] = m;
        g_inv[n * HEADS + hd] = 1.f / (s + 1e-16f);
    }
}

// ------- weight kernel: edge-parallel, one thread per (slot, head) ----------
__global__ void wcalc_kernel(int tot) {
    int t = blockIdx.x * blockDim.x + threadIdx.x;
    if (t >= tot * HEADS) return;
    int slot = t >> 2, hd = t & 3;
    int src = g_srcb[slot], dst = g_dstb[slot];
    float e = g_as[src * HEADS + hd] + g_ad[dst * HEADS + hd];
    e = (e > 0.f) ? e : 0.2f * e;
    float w = __expf(e - g_m[dst * HEADS + hd]) * g_inv[dst * HEADS + hd];
    g_w[t] = w;
}

// ------- pass 2: weighted gather — one warp per (node, head) ----------------
template <bool TO_FEAT>
__global__ void agg2_kernel(const float* bias, float* outext) {
    int gw = (blockIdx.x * blockDim.x + threadIdx.x) >> 5;
    int lane = threadIdx.x & 31;
    if (gw >= NN * HEADS) return;
    int n = gw >> 2, hd = gw & 3;
    int beg = g_ptr[n], end = g_ptr[n + 1];
    const int hoff32 = hd * 32;

    float acc0 = 0.f, acc1 = 0.f;
    int j = beg;
    for (; j + 2 <= end; j += 2) {
        int s0 = g_srcb[j], s1 = g_srcb[j + 1];
        float w0 = g_w[j * HEADS + hd], w1 = g_w[(j + 1) * HEADS + hd];
        uint32_t u0 = g_h16[(long)s0 * 128 + hoff32 + lane];
        uint32_t u1 = g_h16[(long)s1 * 128 + hoff32 + lane];
        float2 f0 = __half22float2(*(__half2*)&u0);
        float2 f1 = __half22float2(*(__half2*)&u1);
        acc0 += w0 * f0.x + w1 * f1.x;
        acc1 += w0 * f0.y + w1 * f1.y;
    }
    if (j < end) {
        int s0 = g_srcb[j];
        float w0 = g_w[j * HEADS + hd];
        uint32_t u0 = g_h16[(long)s0 * 128 + hoff32 + lane];
        float2 f0 = __half22float2(*(__half2*)&u0);
        acc0 += w0 * f0.x;
        acc1 += w0 * f0.y;
    }

    int col = hd * 64 + lane * 2;
    float v0 = acc0 + bias[col];
    float v1 = acc1 + bias[col + 1];
    v0 = (v0 > 0.f) ? v0 : (__expf(v0) - 1.f);  // ELU
    v1 = (v1 > 0.f) ? v1 : (__expf(v1) - 1.f);
    if (TO_FEAT) {
        *(float2*)&g_feat[(long)n * F + col] = make_float2(v0, v1);
    } else {
        *(float2*)&outext[(long)n * F + col] = make_float2(v0, v1);
    }
}

// ---------------- orchestration ----------------
extern "C" void kernel_launch(void* const* d_in, const int* in_sizes, int n_in,
                              void* d_out, int out_size) {
    const float* x   = (const float*)d_in[0];
    const void*  ei  = d_in[1];
    const float* W1  = (const float*)d_in[2];
    const float* a1s = (const float*)d_in[3];
    const float* a1d = (const float*)d_in[4];
    const float* b1  = (const float*)d_in[5];
    const float* W2  = (const float*)d_in[6];
    const float* a2s = (const float*)d_in[7];
    const float* a2d = (const float*)d_in[8];
    const float* b2  = (const float*)d_in[9];
    const float* W3  = (const float*)d_in[10];
    const float* a3s = (const float*)d_in[11];
    const float* a3d = (const float*)d_in[12];
    const float* b3  = (const float*)d_in[13];
    float* out = (float*)d_out;
    int E = in_sizes[1] / 2;
    int tot = E + NN;

    // CSR build (by dst, self loops appended)
    zero_kernel<<<(NN + 255) / 256, 256>>>(ei);
    count_kernel<<<(tot + 255) / 256, 256>>>(ei, E);
    scan_kernel<<<1, 256>>>();
    scatter_kernel<<<(tot + 255) / 256, 256>>>(ei, E);

    dim3 ggrid((NN + 127) / 128, F / 64);
    int p1Blocks = (NN * 32 + 255) / 256;
    int wBlocks = (tot * HEADS + 255) / 256;
    int p2Blocks = (NN * HEADS * 32 + 255) / 256;

    // layer 1
    gemm_tf32_kernel<false><<<ggrid, 256>>>(x, W1, a1s, a1d);
    agg1_kernel<<<p1Blocks, 256>>>();
    wcalc_kernel<<<wBlocks, 256>>>(tot);
    agg2_kernel<true><<<p2Blocks, 256>>>(b1, nullptr);

    // layer 2
    gemm_tf32_kernel<true><<<ggrid, 256>>>(nullptr, W2, a2s, a2d);
    agg1_kernel<<<p1Blocks, 256>>>();
    wcalc_kernel<<<wBlocks, 256>>>(tot);
    agg2_kernel<true><<<p2Blocks, 256>>>(b2, nullptr);

    // layer 3
    gemm_tf32_kernel<true><<<ggrid, 256>>>(nullptr, W3, a3s, a3d);
    agg1_kernel<<<p1Blocks, 256>>>();
    wcalc_kernel<<<wBlocks, 256>>>(tot);
    agg2_kernel<false><<<p2Blocks, 256>>>(b3, out);
}

// round 8
// speedup vs baseline: 1.5704x; 1.0377x over previous
#include <cuda_runtime.h>
#include <cuda_fp16.h>
#include <cstdint>

#define NN    10000
#define HEADS 4
#define F     256      // heads * 64, also input feature count
#define EMAX  340000   // 320000 edges + 10000 self loops, padded

// ---------------- persistent scratch (no allocation allowed) ----------------
__device__ uint32_t g_h16[NN * (F / 2)];   // h as half2 pairs: [node][128]
__device__ float    g_feat[NN * F];        // activated layer output (fp32)
__device__ float    g_as[NN * HEADS];      // per-node src attention logits
__device__ float    g_ad[NN * HEADS];      // per-node dst attention logits
__device__ float    g_w[EMAX * HEADS];     // normalized edge weight per (slot, head)
__device__ int      g_deg[NN];
__device__ int      g_fill[NN];
__device__ int      g_ptr[NN + 1];
__device__ int      g_srcb[EMAX];          // CSR-by-dst: src node per slot
__device__ int      g_is64;                // edge_index dtype flag

// ---------------- zero + edge dtype detection ----------------
__global__ void zero_kernel(const void* eiv) {
    int t = blockIdx.x * blockDim.x + threadIdx.x;
    if (t < NN) { g_deg[t] = 0; g_fill[t] = 0; }
    if (blockIdx.x == 0 && threadIdx.x == 0) {
        const long long* p = (const long long*)eiv;
        int ok = 1;
        for (int i = 0; i < 64; i++) {
            long long v = p[i];
            if (v < 0 || v >= NN) { ok = 0; break; }
        }
        g_is64 = ok;
    }
}

// ---------------- CSR build (4 edges per thread, vectorized) ----------------
// thread ranges: [0, nv) vec-4 edges; [nv, nv+rem) scalar remainder edges;
// [nv+rem, nv+rem+NN) self loops.
__global__ void count_kernel(const void* eiv, int E) {
    int t = blockIdx.x * blockDim.x + threadIdx.x;
    int nv = E >> 2, rem = E & 3;
    if (t < nv) {
        int d0, d1, d2, d3;
        if (!g_is64) {
            const int4* p = (const int4*)((const int*)eiv + E);
            int4 d = p[t];
            d0 = d.x; d1 = d.y; d2 = d.z; d3 = d.w;
        } else {
            const longlong2* p = (const longlong2*)((const long long*)eiv + E);
            longlong2 a = p[2 * t], b = p[2 * t + 1];
            d0 = (int)a.x; d1 = (int)a.y; d2 = (int)b.x; d3 = (int)b.y;
        }
        atomicAdd(&g_deg[d0], 1);
        atomicAdd(&g_deg[d1], 1);
        atomicAdd(&g_deg[d2], 1);
        atomicAdd(&g_deg[d3], 1);
    } else if (t < nv + rem) {
        int idx = E + nv * 4 + (t - nv);
        int d = g_is64 ? (int)((const long long*)eiv)[idx] : ((const int*)eiv)[idx];
        atomicAdd(&g_deg[d], 1);
    } else if (t < nv + rem + NN) {
        atomicAdd(&g_deg[t - nv - rem], 1);  // self loop
    }
}

__global__ void scan_kernel() {
    __shared__ int sdeg[NN];
    __shared__ int wsum[8];
    const int CH = (NN + 255) / 256;  // 40
    int t = threadIdx.x;
    for (int i = t; i < NN; i += 256) sdeg[i] = g_deg[i];
    __syncthreads();

    int base = t * CH;
    int tot = 0;
    for (int i = 0; i < CH; i++) {
        int idx = base + i;
        if (idx < NN) tot += sdeg[idx];
    }
    int lane = t & 31, wid = t >> 5;
    int v = tot;
    for (int off = 1; off < 32; off <<= 1) {
        int u = __shfl_up_sync(0xffffffffu, v, off);
        if (lane >= off) v += u;
    }
    if (lane == 31) wsum[wid] = v;
    __syncthreads();
    if (wid == 0) {
        int w = (lane < 8) ? wsum[lane] : 0;
        for (int off = 1; off < 8; off <<= 1) {
            int u = __shfl_up_sync(0xffffffffu, w, off);
            if (lane >= off) w += u;
        }
        if (lane < 8) wsum[lane] = w;
    }
    __syncthreads();
    int run = v - tot + (wid ? wsum[wid - 1] : 0);
    for (int i = 0; i < CH; i++) {
        int idx = base + i;
        if (idx < NN) {
            int d = sdeg[idx];
            sdeg[idx] = run;
            run += d;
        }
    }
    if (t == 255) g_ptr[NN] = run;
    __syncthreads();
    for (int i = t; i < NN; i += 256) g_ptr[i] = sdeg[i];
}

__global__ void scatter_kernel(const void* eiv, int E) {
    int t = blockIdx.x * blockDim.x + threadIdx.x;
    int nv = E >> 2, rem = E & 3;
    if (t < nv) {
        int s0, s1, s2, s3, d0, d1, d2, d3;
        if (!g_is64) {
            const int4* ps = (const int4*)eiv;
            const int4* pd = (const int4*)((const int*)eiv + E);
            int4 s = ps[t], d = pd[t];
            s0 = s.x; s1 = s.y; s2 = s.z; s3 = s.w;
            d0 = d.x; d1 = d.y; d2 = d.z; d3 = d.w;
        } else {
            const longlong2* ps = (const longlong2*)eiv;
            const longlong2* pd = (const longlong2*)((const long long*)eiv + E);
            longlong2 sa = ps[2 * t], sb = ps[2 * t + 1];
            longlong2 da = pd[2 * t], db = pd[2 * t + 1];
            s0 = (int)sa.x; s1 = (int)sa.y; s2 = (int)sb.x; s3 = (int)sb.y;
            d0 = (int)da.x; d1 = (int)da.y; d2 = (int)db.x; d3 = (int)db.y;
        }
        g_srcb[g_ptr[d0] + atomicAdd(&g_fill[d0], 1)] = s0;
        g_srcb[g_ptr[d1] + atomicAdd(&g_fill[d1], 1)] = s1;
        g_srcb[g_ptr[d2] + atomicAdd(&g_fill[d2], 1)] = s2;
        g_srcb[g_ptr[d3] + atomicAdd(&g_fill[d3], 1)] = s3;
    } else if (t < nv + rem) {
        int off = nv * 4 + (t - nv);
        int s, d;
        if (g_is64) {
            s = (int)((const long long*)eiv)[off];
            d = (int)((const long long*)eiv)[E + off];
        } else {
            s = ((const int*)eiv)[off];
            d = ((const int*)eiv)[E + off];
        }
        g_srcb[g_ptr[d] + atomicAdd(&g_fill[d], 1)] = s;
    } else if (t < nv + rem + NN) {
        int i = t - nv - rem;
        g_srcb[g_ptr[i] + atomicAdd(&g_fill[i], 1)] = i;
    }
}

// ------ tf32 tensor-core GEMM + fused attention dots + fp16 h output --------
__device__ __forceinline__ uint32_t f2tf32(float f) {
    uint32_t r;
    asm("cvt.rna.tf32.f32 %0, %1;" : "=r"(r) : "f"(f));
    return r;
}

template <bool USE_FEAT>
__global__ void __launch_bounds__(256) gemm_tf32_kernel(const float* Aext,
                                                        const float* B,
                                                        const float* att_s,
                                                        const float* att_d) {
    __shared__ uint32_t As[128][36];
    __shared__ uint32_t Bs[32][68];
    __shared__ float sAs[128], sAd[128];
    int tid = threadIdx.x;
    int wid = tid >> 5, lane = tid & 31;
    int wm = wid >> 1, wn = wid & 1;
    int m0 = blockIdx.x * 128, n0 = blockIdx.y * 64;
    int hd = blockIdx.y;

    if (tid < 128) { sAs[tid] = 0.f; sAd[tid] = 0.f; }

    float c[2][4][4];
#pragma unroll
    for (int f = 0; f < 2; f++)
#pragma unroll
        for (int g = 0; g < 4; g++)
#pragma unroll
            for (int i = 0; i < 4; i++) c[f][g][i] = 0.f;

    int lr = lane >> 2;
    int lc = lane & 3;

    for (int kt = 0; kt < F; kt += 32) {
#pragma unroll
        for (int i = 0; i < 4; i++) {
            int id = tid + i * 256;
            int row = id >> 3, c4 = (id & 7) * 4;
            int m = m0 + row;
            float4 v = make_float4(0.f, 0.f, 0.f, 0.f);
            if (m < NN) {
                long off = (long)m * F + kt + c4;
                v = USE_FEAT ? *(const float4*)(&g_feat[off])
                             : *(const float4*)(Aext + off);
            }
            As[row][c4 + 0] = f2tf32(v.x);
            As[row][c4 + 1] = f2tf32(v.y);
            As[row][c4 + 2] = f2tf32(v.z);
            As[row][c4 + 3] = f2tf32(v.w);
        }
#pragma unroll
        for (int i = 0; i < 2; i++) {
            int id = tid + i * 256;
            int row = id >> 4, c4 = (id & 15) * 4;
            float4 v = *(const float4*)(B + (long)(kt + row) * F + n0 + c4);
            Bs[row][c4 + 0] = f2tf32(v.x);
            Bs[row][c4 + 1] = f2tf32(v.y);
            Bs[row][c4 + 2] = f2tf32(v.z);
            Bs[row][c4 + 3] = f2tf32(v.w);
        }
        __syncthreads();

#pragma unroll
        for (int s = 0; s < 4; s++) {
            int kb = s * 8;
            uint32_t a[2][4];
#pragma unroll
            for (int f = 0; f < 2; f++) {
                int rb = wm * 32 + f * 16;
                a[f][0] = As[rb + lr][kb + lc];
                a[f][1] = As[rb + lr + 8][kb + lc];
                a[f][2] = As[rb + lr][kb + lc + 4];
                a[f][3] = As[rb + lr + 8][kb + lc + 4];
            }
            uint32_t b[4][2];
#pragma unroll
            for (int g = 0; g < 4; g++) {
                int cb = wn * 32 + g * 8;
                b[g][0] = Bs[kb + lc][cb + lr];
                b[g][1] = Bs[kb + lc + 4][cb + lr];
            }
#pragma unroll
            for (int f = 0; f < 2; f++)
#pragma unroll
                for (int g = 0; g < 4; g++) {
                    asm volatile(
                        "mma.sync.aligned.m16n8k8.row.col.f32.tf32.tf32.f32 "
                        "{%0,%1,%2,%3}, {%4,%5,%6,%7}, {%8,%9}, {%0,%1,%2,%3};"
                        : "+f"(c[f][g][0]), "+f"(c[f][g][1]),
                          "+f"(c[f][g][2]), "+f"(c[f][g][3])
                        : "r"(a[f][0]), "r"(a[f][1]), "r"(a[f][2]), "r"(a[f][3]),
                          "r"(b[g][0]), "r"(b[g][1]));
                }
        }
        __syncthreads();
    }

    // epilogue: write h as half2, fused per-row attention dots (fp32)
#pragma unroll
    for (int f = 0; f < 2; f++) {
        int row0 = m0 + wm * 32 + f * 16 + lr;
        float ps0 = 0.f, ps1 = 0.f, pd0 = 0.f, pd1 = 0.f;
#pragma unroll
        for (int g = 0; g < 4; g++) {
            int colh = wn * 32 + g * 8 + lc * 2;        // column within head
            float as0 = att_s[hd * 64 + colh], as1 = att_s[hd * 64 + colh + 1];
            float ad0 = att_d[hd * 64 + colh], ad1 = att_d[hd * 64 + colh + 1];
            ps0 += c[f][g][0] * as0 + c[f][g][1] * as1;
            pd0 += c[f][g][0] * ad0 + c[f][g][1] * ad1;
            ps1 += c[f][g][2] * as0 + c[f][g][3] * as1;
            pd1 += c[f][g][2] * ad0 + c[f][g][3] * ad1;
            uint32_t hidx = (uint32_t)(wn * 16 + g * 4 + lc) + hd * 32;
            if (row0 < NN) {
                __half2 hv = __floats2half2_rn(c[f][g][0], c[f][g][1]);
                g_h16[(long)row0 * 128 + hidx] = *(uint32_t*)&hv;
            }
            if (row0 + 8 < NN) {
                __half2 hv = __floats2half2_rn(c[f][g][2], c[f][g][3]);
                g_h16[(long)(row0 + 8) * 128 + hidx] = *(uint32_t*)&hv;
            }
        }
#pragma unroll
        for (int off = 1; off <= 2; off <<= 1) {
            ps0 += __shfl_xor_sync(0xffffffffu, ps0, off);
            ps1 += __shfl_xor_sync(0xffffffffu, ps1, off);
            pd0 += __shfl_xor_sync(0xffffffffu, pd0, off);
            pd1 += __shfl_xor_sync(0xffffffffu, pd1, off);
        }
        if (lc == 0) {
            int r = wm * 32 + f * 16 + lr;
            atomicAdd(&sAs[r], ps0);
            atomicAdd(&sAd[r], pd0);
            atomicAdd(&sAs[r + 8], ps1);
            atomicAdd(&sAd[r + 8], pd1);
        }
    }
    __syncthreads();
    if (tid < 128) {
        int m = m0 + tid;
        if (m < NN) {
            g_as[m * HEADS + hd] = sAs[tid];
            g_ad[m * HEADS + hd] = sAd[tid];
        }
    }
}

// ------- pass 1 + weights: one warp per node, all 4 heads -------------------
// lane = sub*4 + hd. First sweep: online (max,sum). Butterfly over offsets
// 4/8/16 reduces across sub while staying within the same head. Second sweep
// recomputes e (L1-hot) and stores normalized weights, coalesced.
__global__ void agg1w_kernel() {
    int n = (blockIdx.x * blockDim.x + threadIdx.x) >> 5;
    int lane = threadIdx.x & 31;
    if (n >= NN) return;
    int hd = lane & 3, sub = lane >> 2;
    int beg = g_ptr[n], end = g_ptr[n + 1];
    float ad = g_ad[n * HEADS + hd];

    float m = -1e30f, s = 0.f;
    for (int j = beg + sub; j < end; j += 8) {
        int src = g_srcb[j];
        float e = g_as[src * HEADS + hd] + ad;
        e = (e > 0.f) ? e : 0.2f * e;
        float mn = fmaxf(m, e);
        s = s * __expf(m - mn) + __expf(e - mn);
        m = mn;
    }
#pragma unroll
    for (int off = 4; off <= 16; off <<= 1) {
        float m2 = __shfl_xor_sync(0xffffffffu, m, off);
        float s2 = __shfl_xor_sync(0xffffffffu, s, off);
        float mn = fmaxf(m, m2);
        s = s * __expf(m - mn) + s2 * __expf(m2 - mn);
        m = mn;
    }
    float inv = 1.f / (s + 1e-16f);

    for (int j = beg + sub; j < end; j += 8) {
        int src = g_srcb[j];
        float e = g_as[src * HEADS + hd] + ad;
        e = (e > 0.f) ? e : 0.2f * e;
        g_w[j * HEADS + hd] = __expf(e - m) * inv;
    }
}

// ------- pass 2: weighted gather — one warp per (node, head) ----------------
template <bool TO_FEAT>
__global__ void agg2_kernel(const float* bias, float* outext) {
    int gw = (blockIdx.x * blockDim.x + threadIdx.x) >> 5;
    int lane = threadIdx.x & 31;
    if (gw >= NN * HEADS) return;
    int n = gw >> 2, hd = gw & 3;
    int beg = g_ptr[n], end = g_ptr[n + 1];
    const int hoff32 = hd * 32;

    float acc0 = 0.f, acc1 = 0.f;
    int j = beg;
    for (; j + 2 <= end; j += 2) {
        int s0 = g_srcb[j], s1 = g_srcb[j + 1];
        float w0 = g_w[j * HEADS + hd], w1 = g_w[(j + 1) * HEADS + hd];
        uint32_t u0 = g_h16[(long)s0 * 128 + hoff32 + lane];
        uint32_t u1 = g_h16[(long)s1 * 128 + hoff32 + lane];
        float2 f0 = __half22float2(*(__half2*)&u0);
        float2 f1 = __half22float2(*(__half2*)&u1);
        acc0 += w0 * f0.x + w1 * f1.x;
        acc1 += w0 * f0.y + w1 * f1.y;
    }
    if (j < end) {
        int s0 = g_srcb[j];
        float w0 = g_w[j * HEADS + hd];
        uint32_t u0 = g_h16[(long)s0 * 128 + hoff32 + lane];
        float2 f0 = __half22float2(*(__half2*)&u0);
        acc0 += w0 * f0.x;
        acc1 += w0 * f0.y;
    }

    int col = hd * 64 + lane * 2;
    float v0 = acc0 + bias[col];
    float v1 = acc1 + bias[col + 1];
    v0 = (v0 > 0.f) ? v0 : (__expf(v0) - 1.f);  // ELU
    v1 = (v1 > 0.f) ? v1 : (__expf(v1) - 1.f);
    if (TO_FEAT) {
        *(float2*)&g_feat[(long)n * F + col] = make_float2(v0, v1);
    } else {
        *(float2*)&outext[(long)n * F + col] = make_float2(v0, v1);
    }
}

// ---------------- orchestration ----------------
extern "C" void kernel_launch(void* const* d_in, const int* in_sizes, int n_in,
                              void* d_out, int out_size) {
    const float* x   = (const float*)d_in[0];
    const void*  ei  = d_in[1];
    const float* W1  = (const float*)d_in[2];
    const float* a1s = (const float*)d_in[3];
    const float* a1d = (const float*)d_in[4];
    const float* b1  = (const float*)d_in[5];
    const float* W2  = (const float*)d_in[6];
    const float* a2s = (const float*)d_in[7];
    const float* a2d = (const float*)d_in[8];
    const float* b2  = (const float*)d_in[9];
    const float* W3  = (const float*)d_in[10];
    const float* a3s = (const float*)d_in[11];
    const float* a3d = (const float*)d_in[12];
    const float* b3  = (const float*)d_in[13];
    float* out = (float*)d_out;
    int E = in_sizes[1] / 2;
    int nthreads = (E >> 2) + (E & 3) + NN;   // vec threads + remainder + loops

    // CSR build (by dst, self loops appended)
    zero_kernel<<<(NN + 255) / 256, 256>>>(ei);
    count_kernel<<<(nthreads + 255) / 256, 256>>>(ei, E);
    scan_kernel<<<1, 256>>>();
    scatter_kernel<<<(nthreads + 255) / 256, 256>>>(ei, E);

    dim3 ggrid((NN + 127) / 128, F / 64);
    int p1Blocks = (NN * 32 + 255) / 256;
    int p2Blocks = (NN * HEADS * 32 + 255) / 256;

    // layer 1
    gemm_tf32_kernel<false><<<ggrid, 256>>>(x, W1, a1s, a1d);
    agg1w_kernel<<<p1Blocks, 256>>>();
    agg2_kernel<true><<<p2Blocks, 256>>>(b1, nullptr);

    // layer 2
    gemm_tf32_kernel<true><<<ggrid, 256>>>(nullptr, W2, a2s, a2d);
    agg1w_kernel<<<p1Blocks, 256>>>();
    agg2_kernel<true><<<p2Blocks, 256>>>(b2, nullptr);

    // layer 3
    gemm_tf32_kernel<true><<<ggrid, 256>>>(nullptr, W3, a3s, a3d);
    agg1w_kernel<<<p1Blocks, 256>>>();
    agg2_kernel<false><<<p2Blocks, 256>>>(b3, out);
}

// round 9
// speedup vs baseline: 1.7595x; 1.1204x over previous
#include <cuda_runtime.h>
#include <cuda_fp16.h>
#include <cstdint>

#define NN    10000
#define HEADS 4
#define F     256      // heads * 64, also input feature count
#define EMAX  340000   // 320000 edges + 10000 self loops, padded

// ---------------- persistent scratch (no allocation allowed) ----------------
__device__ uint32_t g_h16[NN * (F / 2)];   // h as half2 pairs: [node][128]
__device__ float    g_feat[NN * F];        // activated layer output (fp32)
__device__ float    g_as[NN * HEADS];      // per-node src attention logits
__device__ float    g_ad[NN * HEADS];      // per-node dst attention logits
__device__ float    g_w[EMAX * HEADS];     // normalized edge weight per (slot, head)
__device__ int      g_deg[NN];
__device__ int      g_ptr[NN + 1];
__device__ int      g_epos[EMAX];          // per-edge position within its dst bucket
__device__ int      g_srcb[EMAX];          // CSR-by-dst: src node per slot
__device__ int      g_is64;                // edge_index dtype flag

// ---------------- zero + edge dtype detection ----------------
__global__ void zero_kernel(const void* eiv) {
    int t = blockIdx.x * blockDim.x + threadIdx.x;
    if (t < NN) g_deg[t] = 0;
    if (blockIdx.x == 0 && threadIdx.x == 0) {
        const long long* p = (const long long*)eiv;
        int ok = 1;
        for (int i = 0; i < 64; i++) {
            long long v = p[i];
            if (v < 0 || v >= NN) { ok = 0; break; }
        }
        g_is64 = ok;
    }
}

// ---------------- CSR build ----------------
// count: atomically count in-degree AND record each edge's position within
// its dst bucket (coalesced store). Self loops occupy epos slots [E, E+NN).
__global__ void count_kernel(const void* eiv, int E) {
    int t = blockIdx.x * blockDim.x + threadIdx.x;
    int nv = E >> 2, rem = E & 3;
    if (t < nv) {
        int d0, d1, d2, d3;
        if (!g_is64) {
            const int4* p = (const int4*)((const int*)eiv + E);
            int4 d = p[t];
            d0 = d.x; d1 = d.y; d2 = d.z; d3 = d.w;
        } else {
            const longlong2* p = (const longlong2*)((const long long*)eiv + E);
            longlong2 a = p[2 * t], b = p[2 * t + 1];
            d0 = (int)a.x; d1 = (int)a.y; d2 = (int)b.x; d3 = (int)b.y;
        }
        int4 pos;
        pos.x = atomicAdd(&g_deg[d0], 1);
        pos.y = atomicAdd(&g_deg[d1], 1);
        pos.z = atomicAdd(&g_deg[d2], 1);
        pos.w = atomicAdd(&g_deg[d3], 1);
        *(int4*)&g_epos[t * 4] = pos;
    } else if (t < nv + rem) {
        int idx = nv * 4 + (t - nv);
        int d = g_is64 ? (int)((const long long*)eiv)[E + idx]
                       : ((const int*)eiv)[E + idx];
        g_epos[idx] = atomicAdd(&g_deg[d], 1);
    } else if (t < nv + rem + NN) {
        int i = t - nv - rem;
        g_epos[E + i] = atomicAdd(&g_deg[i], 1);  // self loop
    }
}

__global__ void scan_kernel() {
    __shared__ int sdeg[NN];
    __shared__ int wsum[8];
    const int CH = (NN + 255) / 256;  // 40
    int t = threadIdx.x;
    for (int i = t; i < NN; i += 256) sdeg[i] = g_deg[i];
    __syncthreads();

    int base = t * CH;
    int tot = 0;
    for (int i = 0; i < CH; i++) {
        int idx = base + i;
        if (idx < NN) tot += sdeg[idx];
    }
    int lane = t & 31, wid = t >> 5;
    int v = tot;
    for (int off = 1; off < 32; off <<= 1) {
        int u = __shfl_up_sync(0xffffffffu, v, off);
        if (lane >= off) v += u;
    }
    if (lane == 31) wsum[wid] = v;
    __syncthreads();
    if (wid == 0) {
        int w = (lane < 8) ? wsum[lane] : 0;
        for (int off = 1; off < 8; off <<= 1) {
            int u = __shfl_up_sync(0xffffffffu, w, off);
            if (lane >= off) w += u;
        }
        if (lane < 8) wsum[lane] = w;
    }
    __syncthreads();
    int run = v - tot + (wid ? wsum[wid - 1] : 0);
    for (int i = 0; i < CH; i++) {
        int idx = base + i;
        if (idx < NN) {
            int d = sdeg[idx];
            sdeg[idx] = run;
            run += d;
        }
    }
    if (t == 255) g_ptr[NN] = run;
    __syncthreads();
    for (int i = t; i < NN; i += 256) g_ptr[i] = sdeg[i];
}

// scatter: NO atomics — slot = g_ptr[dst] + precomputed position.
__global__ void scatter_kernel(const void* eiv, int E) {
    int t = blockIdx.x * blockDim.x + threadIdx.x;
    int nv = E >> 2, rem = E & 3;
    if (t < nv) {
        int s0, s1, s2, s3, d0, d1, d2, d3;
        if (!g_is64) {
            const int4* ps = (const int4*)eiv;
            const int4* pd = (const int4*)((const int*)eiv + E);
            int4 s = ps[t], d = pd[t];
            s0 = s.x; s1 = s.y; s2 = s.z; s3 = s.w;
            d0 = d.x; d1 = d.y; d2 = d.z; d3 = d.w;
        } else {
            const longlong2* ps = (const longlong2*)eiv;
            const longlong2* pd = (const longlong2*)((const long long*)eiv + E);
            longlong2 sa = ps[2 * t], sb = ps[2 * t + 1];
            longlong2 da = pd[2 * t], db = pd[2 * t + 1];
            s0 = (int)sa.x; s1 = (int)sa.y; s2 = (int)sb.x; s3 = (int)sb.y;
            d0 = (int)da.x; d1 = (int)da.y; d2 = (int)db.x; d3 = (int)db.y;
        }
        int4 pos = *(const int4*)&g_epos[t * 4];
        g_srcb[g_ptr[d0] + pos.x] = s0;
        g_srcb[g_ptr[d1] + pos.y] = s1;
        g_srcb[g_ptr[d2] + pos.z] = s2;
        g_srcb[g_ptr[d3] + pos.w] = s3;
    } else if (t < nv + rem) {
        int idx = nv * 4 + (t - nv);
        int s, d;
        if (g_is64) {
            s = (int)((const long long*)eiv)[idx];
            d = (int)((const long long*)eiv)[E + idx];
        } else {
            s = ((const int*)eiv)[idx];
            d = ((const int*)eiv)[E + idx];
        }
        g_srcb[g_ptr[d] + g_epos[idx]] = s;
    } else if (t < nv + rem + NN) {
        int i = t - nv - rem;
        g_srcb[g_ptr[i] + g_epos[E + i]] = i;
    }
}

// ------ tf32 tensor-core GEMM + fused attention dots + fp16 h output --------
__device__ __forceinline__ uint32_t f2tf32(float f) {
    uint32_t r;
    asm("cvt.rna.tf32.f32 %0, %1;" : "=r"(r) : "f"(f));
    return r;
}

template <bool USE_FEAT>
__global__ void __launch_bounds__(256) gemm_tf32_kernel(const float* Aext,
                                                        const float* B,
                                                        const float* att_s,
                                                        const float* att_d) {
    __shared__ uint32_t As[128][36];
    __shared__ uint32_t Bs[32][72];   // pad 72: b-frag bank = (lc*8+lr)%32, conflict-free
    __shared__ float sAs[128], sAd[128];
    int tid = threadIdx.x;
    int wid = tid >> 5, lane = tid & 31;
    int wm = wid >> 1, wn = wid & 1;
    int m0 = blockIdx.x * 128, n0 = blockIdx.y * 64;
    int hd = blockIdx.y;

    if (tid < 128) { sAs[tid] = 0.f; sAd[tid] = 0.f; }

    float c[2][4][4];
#pragma unroll
    for (int f = 0; f < 2; f++)
#pragma unroll
        for (int g = 0; g < 4; g++)
#pragma unroll
            for (int i = 0; i < 4; i++) c[f][g][i] = 0.f;

    int lr = lane >> 2;
    int lc = lane & 3;

    for (int kt = 0; kt < F; kt += 32) {
#pragma unroll
        for (int i = 0; i < 4; i++) {
            int id = tid + i * 256;
            int row = id >> 3, c4 = (id & 7) * 4;
            int m = m0 + row;
            float4 v = make_float4(0.f, 0.f, 0.f, 0.f);
            if (m < NN) {
                long off = (long)m * F + kt + c4;
                v = USE_FEAT ? *(const float4*)(&g_feat[off])
                             : *(const float4*)(Aext + off);
            }
            As[row][c4 + 0] = f2tf32(v.x);
            As[row][c4 + 1] = f2tf32(v.y);
            As[row][c4 + 2] = f2tf32(v.z);
            As[row][c4 + 3] = f2tf32(v.w);
        }
#pragma unroll
        for (int i = 0; i < 2; i++) {
            int id = tid + i * 256;
            int row = id >> 4, c4 = (id & 15) * 4;
            float4 v = *(const float4*)(B + (long)(kt + row) * F + n0 + c4);
            Bs[row][c4 + 0] = f2tf32(v.x);
            Bs[row][c4 + 1] = f2tf32(v.y);
            Bs[row][c4 + 2] = f2tf32(v.z);
            Bs[row][c4 + 3] = f2tf32(v.w);
        }
        __syncthreads();

#pragma unroll
        for (int s = 0; s < 4; s++) {
            int kb = s * 8;
            uint32_t a[2][4];
#pragma unroll
            for (int f = 0; f < 2; f++) {
                int rb = wm * 32 + f * 16;
                a[f][0] = As[rb + lr][kb + lc];
                a[f][1] = As[rb + lr + 8][kb + lc];
                a[f][2] = As[rb + lr][kb + lc + 4];
                a[f][3] = As[rb + lr + 8][kb + lc + 4];
            }
            uint32_t b[4][2];
#pragma unroll
            for (int g = 0; g < 4; g++) {
                int cb = wn * 32 + g * 8;
                b[g][0] = Bs[kb + lc][cb + lr];
                b[g][1] = Bs[kb + lc + 4][cb + lr];
            }
#pragma unroll
            for (int f = 0; f < 2; f++)
#pragma unroll
                for (int g = 0; g < 4; g++) {
                    asm volatile(
                        "mma.sync.aligned.m16n8k8.row.col.f32.tf32.tf32.f32 "
                        "{%0,%1,%2,%3}, {%4,%5,%6,%7}, {%8,%9}, {%0,%1,%2,%3};"
                        : "+f"(c[f][g][0]), "+f"(c[f][g][1]),
                          "+f"(c[f][g][2]), "+f"(c[f][g][3])
                        : "r"(a[f][0]), "r"(a[f][1]), "r"(a[f][2]), "r"(a[f][3]),
                          "r"(b[g][0]), "r"(b[g][1]));
                }
        }
        __syncthreads();
    }

    // epilogue: write h as half2, fused per-row attention dots (fp32)
#pragma unroll
    for (int f = 0; f < 2; f++) {
        int row0 = m0 + wm * 32 + f * 16 + lr;
        float ps0 = 0.f, ps1 = 0.f, pd0 = 0.f, pd1 = 0.f;
#pragma unroll
        for (int g = 0; g < 4; g++) {
            int colh = wn * 32 + g * 8 + lc * 2;        // column within head
            float as0 = att_s[hd * 64 + colh], as1 = att_s[hd * 64 + colh + 1];
            float ad0 = att_d[hd * 64 + colh], ad1 = att_d[hd * 64 + colh + 1];
            ps0 += c[f][g][0] * as0 + c[f][g][1] * as1;
            pd0 += c[f][g][0] * ad0 + c[f][g][1] * ad1;
            ps1 += c[f][g][2] * as0 + c[f][g][3] * as1;
            pd1 += c[f][g][2] * ad0 + c[f][g][3] * ad1;
            uint32_t hidx = (uint32_t)(wn * 16 + g * 4 + lc) + hd * 32;
            if (row0 < NN) {
                __half2 hv = __floats2half2_rn(c[f][g][0], c[f][g][1]);
                g_h16[(long)row0 * 128 + hidx] = *(uint32_t*)&hv;
            }
            if (row0 + 8 < NN) {
                __half2 hv = __floats2half2_rn(c[f][g][2], c[f][g][3]);
                g_h16[(long)(row0 + 8) * 128 + hidx] = *(uint32_t*)&hv;
            }
        }
#pragma unroll
        for (int off = 1; off <= 2; off <<= 1) {
            ps0 += __shfl_xor_sync(0xffffffffu, ps0, off);
            ps1 += __shfl_xor_sync(0xffffffffu, ps1, off);
            pd0 += __shfl_xor_sync(0xffffffffu, pd0, off);
            pd1 += __shfl_xor_sync(0xffffffffu, pd1, off);
        }
        if (lc == 0) {
            int r = wm * 32 + f * 16 + lr;
            atomicAdd(&sAs[r], ps0);
            atomicAdd(&sAd[r], pd0);
            atomicAdd(&sAs[r + 8], ps1);
            atomicAdd(&sAd[r + 8], pd1);
        }
    }
    __syncthreads();
    if (tid < 128) {
        int m = m0 + tid;
        if (m < NN) {
            g_as[m * HEADS + hd] = sAs[tid];
            g_ad[m * HEADS + hd] = sAd[tid];
        }
    }
}

// ------- pass 1 + weights: one warp per node, all 4 heads -------------------
__global__ void agg1w_kernel() {
    int n = (blockIdx.x * blockDim.x + threadIdx.x) >> 5;
    int lane = threadIdx.x & 31;
    if (n >= NN) return;
    int hd = lane & 3, sub = lane >> 2;
    int beg = g_ptr[n], end = g_ptr[n + 1];
    float ad = g_ad[n * HEADS + hd];

    float m = -1e30f, s = 0.f;
    for (int j = beg + sub; j < end; j += 8) {
        int src = g_srcb[j];
        float e = g_as[src * HEADS + hd] + ad;
        e = (e > 0.f) ? e : 0.2f * e;
        float mn = fmaxf(m, e);
        s = s * __expf(m - mn) + __expf(e - mn);
        m = mn;
    }
#pragma unroll
    for (int off = 4; off <= 16; off <<= 1) {
        float m2 = __shfl_xor_sync(0xffffffffu, m, off);
        float s2 = __shfl_xor_sync(0xffffffffu, s, off);
        float mn = fmaxf(m, m2);
        s = s * __expf(m - mn) + s2 * __expf(m2 - mn);
        m = mn;
    }
    float inv = 1.f / (s + 1e-16f);

    for (int j = beg + sub; j < end; j += 8) {
        int src = g_srcb[j];
        float e = g_as[src * HEADS + hd] + ad;
        e = (e > 0.f) ? e : 0.2f * e;
        g_w[j * HEADS + hd] = __expf(e - m) * inv;
    }
}

// ------- pass 2: weighted gather — one warp per (node, head), 4-wide MLP ----
template <bool TO_FEAT>
__global__ void agg2_kernel(const float* bias, float* outext) {
    int gw = (blockIdx.x * blockDim.x + threadIdx.x) >> 5;
    int lane = threadIdx.x & 31;
    if (gw >= NN * HEADS) return;
    int n = gw >> 2, hd = gw & 3;
    int beg = g_ptr[n], end = g_ptr[n + 1];
    const int hoff32 = hd * 32;

    float acc0 = 0.f, acc1 = 0.f;
    int j = beg;
    for (; j + 4 <= end; j += 4) {
        int s0 = g_srcb[j],     s1 = g_srcb[j + 1];
        int s2 = g_srcb[j + 2], s3 = g_srcb[j + 3];
        float w0 = g_w[(j + 0) * HEADS + hd], w1 = g_w[(j + 1) * HEADS + hd];
        float w2 = g_w[(j + 2) * HEADS + hd], w3 = g_w[(j + 3) * HEADS + hd];
        uint32_t u0 = g_h16[(long)s0 * 128 + hoff32 + lane];
        uint32_t u1 = g_h16[(long)s1 * 128 + hoff32 + lane];
        uint32_t u2 = g_h16[(long)s2 * 128 + hoff32 + lane];
        uint32_t u3 = g_h16[(long)s3 * 128 + hoff32 + lane];
        float2 f0 = __half22float2(*(__half2*)&u0);
        float2 f1 = __half22float2(*(__half2*)&u1);
        float2 f2 = __half22float2(*(__half2*)&u2);
        float2 f3 = __half22float2(*(__half2*)&u3);
        acc0 += w0 * f0.x + w1 * f1.x + w2 * f2.x + w3 * f3.x;
        acc1 += w0 * f0.y + w1 * f1.y + w2 * f2.y + w3 * f3.y;
    }
    for (; j < end; ++j) {
        int s0 = g_srcb[j];
        float w0 = g_w[j * HEADS + hd];
        uint32_t u0 = g_h16[(long)s0 * 128 + hoff32 + lane];
        float2 f0 = __half22float2(*(__half2*)&u0);
        acc0 += w0 * f0.x;
        acc1 += w0 * f0.y;
    }

    int col = hd * 64 + lane * 2;
    float v0 = acc0 + bias[col];
    float v1 = acc1 + bias[col + 1];
    v0 = (v0 > 0.f) ? v0 : (__expf(v0) - 1.f);  // ELU
    v1 = (v1 > 0.f) ? v1 : (__expf(v1) - 1.f);
    if (TO_FEAT) {
        *(float2*)&g_feat[(long)n * F + col] = make_float2(v0, v1);
    } else {
        *(float2*)&outext[(long)n * F + col] = make_float2(v0, v1);
    }
}

// ---------------- orchestration ----------------
extern "C" void kernel_launch(void* const* d_in, const int* in_sizes, int n_in,
                              void* d_out, int out_size) {
    const float* x   = (const float*)d_in[0];
    const void*  ei  = d_in[1];
    const float* W1  = (const float*)d_in[2];
    const float* a1s = (const float*)d_in[3];
    const float* a1d = (const float*)d_in[4];
    const float* b1  = (const float*)d_in[5];
    const float* W2  = (const float*)d_in[6];
    const float* a2s = (const float*)d_in[7];
    const float* a2d = (const float*)d_in[8];
    const float* b2  = (const float*)d_in[9];
    const float* W3  = (const float*)d_in[10];
    const float* a3s = (const float*)d_in[11];
    const float* a3d = (const float*)d_in[12];
    const float* b3  = (const float*)d_in[13];
    float* out = (float*)d_out;
    int E = in_sizes[1] / 2;
    int nthreads = (E >> 2) + (E & 3) + NN;   // vec threads + remainder + loops

    // CSR build (by dst, self loops appended)
    zero_kernel<<<(NN + 255) / 256, 256>>>(ei);
    count_kernel<<<(nthreads + 255) / 256, 256>>>(ei, E);
    scan_kernel<<<1, 256>>>();
    scatter_kernel<<<(nthreads + 255) / 256, 256>>>(ei, E);

    dim3 ggrid((NN + 127) / 128, F / 64);
    int p1Blocks = (NN * 32 + 255) / 256;
    int p2Blocks = (NN * HEADS * 32 + 255) / 256;

    // layer 1
    gemm_tf32_kernel<false><<<ggrid, 256>>>(x, W1, a1s, a1d);
    agg1w_kernel<<<p1Blocks, 256>>>();
    agg2_kernel<true><<<p2Blocks, 256>>>(b1, nullptr);

    // layer 2
    gemm_tf32_kernel<true><<<ggrid, 256>>>(nullptr, W2, a2s, a2d);
    agg1w_kernel<<<p1Blocks, 256>>>();
    agg2_kernel<true><<<p2Blocks, 256>>>(b2, nullptr);

    // layer 3
    gemm_tf32_kernel<true><<<ggrid, 256>>>(nullptr, W3, a3s, a3d);
    agg1w_kernel<<<p1Blocks, 256>>>();
    agg2_kernel<false><<<p2Blocks, 256>>>(b3, out);
}